// round 7
// baseline (speedup 1.0000x reference)
#include <cuda_runtime.h>
#include <math.h>

#define HN   16
#define KVN  8
#define HDIM 64
#define WIN  512
#define BATCH 2
#define SEQ  2048
#define DM   1024

// Scratch — layouts:
// g_q: [B, HN, S, 64], g_k/g_v: [B, KVN, S, 64], g_attn: [B*S, HN*64]
__device__ float g_q[(size_t)BATCH * HN * SEQ * HDIM];
__device__ float g_k[(size_t)BATCH * KVN * SEQ * HDIM];
__device__ float g_v[(size_t)BATCH * KVN * SEQ * HDIM];
__device__ float g_attn[(size_t)BATCH * SEQ * HN * HDIM];
// RoPE tables: [SEQ][32]
__device__ float g_cos[SEQ * 32];
__device__ float g_sin[SEQ * 32];

// ---------------------------------------------------------------------------
// RoPE table, double-precision trig (immune to --use_fast_math).
// ---------------------------------------------------------------------------
__global__ void build_rope_table()
{
    const int idx = blockIdx.x * blockDim.x + threadIdx.x;
    if (idx >= SEQ * 32) return;
    const int p = idx & 31;
    const int s = idx >> 5;
    const double invf = pow(10000.0, -((double)(2 * p)) / 64.0);
    const double ang = (double)s * invf;
    g_cos[idx] = (float)cos(ang);
    g_sin[idx] = (float)sin(ang);
}

__global__ void rope_apply(float* __restrict__ x, int rows)
{
    const int idx = blockIdx.x * blockDim.x + threadIdx.x;
    if (idx >= rows * SEQ * 32) return;
    const int p = idx & 31;
    const int s = (idx >> 5) & (SEQ - 1);

    const float c  = g_cos[(s << 5) | p];
    const float sn = g_sin[(s << 5) | p];

    float* base = x + (size_t)(idx >> 5) * HDIM;
    const float x1 = base[p];
    const float x2 = base[p + 32];
    base[p]      = x1 * c - x2 * sn;
    base[p + 32] = x2 * c + x1 * sn;
}

// ---------------------------------------------------------------------------
// gemm128: C = A[M,K] @ B[K,N]. BM=BN=128, BK=16, 256 threads, 8x8/thr with
// split fragments (rows ty*4 / ty*4+64, cols tx*4 / tx*4+64) for
// conflict-free LDS.128. MODE 0: linear C. MODE 1: scatter to head layout.
// ---------------------------------------------------------------------------
template <int MODE>
__global__ void __launch_bounds__(256)
gemm128(const float* __restrict__ A, const float* __restrict__ Bm,
        float* __restrict__ C, int M, int N, int K, int NH)
{
    __shared__ float As[16][132];   // [k][m], padded (132 % 4 == 0 for f4 reads)
    __shared__ float Bs[16][132];   // [k][n]

    const int tid = threadIdx.x;
    const int tx = tid & 15;        // col group
    const int ty = tid >> 4;        // row group
    const int m0 = blockIdx.y * 128, n0 = blockIdx.x * 128;

    float acc[8][8] = {};

    for (int k0 = 0; k0 < K; k0 += 16) {
#pragma unroll
        for (int i0 = 0; i0 < 2; i0++) {
            const int i = tid + i0 * 256;
            // A: 512 float4 loads, transpose into As[k][m]
            const int r = i >> 2, c = (i & 3) * 4;
            float4 av = *(const float4*)(A + (size_t)(m0 + r) * K + k0 + c);
            As[c + 0][r] = av.x; As[c + 1][r] = av.y;
            As[c + 2][r] = av.z; As[c + 3][r] = av.w;
            // B: rows 0..15, 32 float4 per row
            const int br = i >> 5, bc = (i & 31) * 4;
            *(float4*)(&Bs[br][bc]) =
                *(const float4*)(Bm + (size_t)(k0 + br) * N + n0 + bc);
        }
        __syncthreads();

#pragma unroll
        for (int kk = 0; kk < 16; kk++) {
            float a[8], b[8];
            *(float4*)(a)     = *(const float4*)(&As[kk][ty * 4]);
            *(float4*)(a + 4) = *(const float4*)(&As[kk][64 + ty * 4]);
            *(float4*)(b)     = *(const float4*)(&Bs[kk][tx * 4]);
            *(float4*)(b + 4) = *(const float4*)(&Bs[kk][64 + tx * 4]);
#pragma unroll
            for (int i = 0; i < 8; i++)
#pragma unroll
                for (int j = 0; j < 8; j++)
                    acc[i][j] += a[i] * b[j];
        }
        __syncthreads();
    }

    // Store: rows r(i) = (i<4 ? ty*4+i : 64+ty*4+i-4), cols c(jg) similar.
#pragma unroll
    for (int i = 0; i < 8; i++) {
        const int lr = (i < 4) ? (ty * 4 + i) : (64 + ty * 4 + i - 4);
#pragma unroll
        for (int jg = 0; jg < 2; jg++) {
            const int lc = (jg == 0) ? (tx * 4) : (64 + tx * 4);
            float4 o = make_float4(acc[i][jg * 4 + 0], acc[i][jg * 4 + 1],
                                   acc[i][jg * 4 + 2], acc[i][jg * 4 + 3]);
            if (MODE == 0) {
                *(float4*)(C + (size_t)(m0 + lr) * N + n0 + lc) = o;
            } else {
                const int bb = m0 / SEQ, s0 = m0 % SEQ;
                const int n = n0 + lc;
                const int hh = n >> 6, d = n & 63;
                *(float4*)(C + (((size_t)(bb * NH + hh)) * SEQ + s0 + lr) * HDIM + d) = o;
            }
        }
    }
}

// ---------------------------------------------------------------------------
// Attention: 128 threads = one 64-query tile, 2 threads per query row
// (each owns 32 dims). Score via shfl_xor(1); softmax state redundant per pair.
// ---------------------------------------------------------------------------
__global__ void __launch_bounds__(128) attn_kernel()
{
    __shared__ float Ks[64][68];
    __shared__ float Vs[64][68];

    const int b = blockIdx.z, h = blockIdx.y;
    const int qb = blockIdx.x * 64;
    const int kvh = h >> 1;            // n_rep = 2
    const int tid = threadIdx.x;
    const int row = tid >> 1;          // query row in tile
    const int half = tid & 1;          // which 32-dim half
    const int qi = qb + row;
    const int d0 = half * 8;           // float4 offset into the 16 groups

    const float* qg = g_q + ((size_t)(b * HN + h) * SEQ + qb) * HDIM;
    const float* kg = g_k + (size_t)(b * KVN + kvh) * SEQ * HDIM;
    const float* vg = g_v + (size_t)(b * KVN + kvh) * SEQ * HDIM;

    // Stage Q tile via Ks (coalesced), pull own half-row into registers.
    for (int i = tid; i < 64 * 16; i += 128) {
        const int f = i * 4;
        *(float4*)(&Ks[f >> 6][f & 63]) = *(const float4*)(qg + f);
    }
    __syncthreads();
    float4 q4[8];
#pragma unroll
    for (int d = 0; d < 8; d++) q4[d] = *(float4*)(&Ks[row][(d0 + d) * 4]);
    __syncthreads();

    float4 av[8];
#pragma unroll
    for (int d = 0; d < 8; d++) av[d] = make_float4(0.f, 0.f, 0.f, 0.f);
    float m = -1e30f, l = 0.0f;

    const int kstart = (qb >= WIN) ? (qb - WIN) : 0;

    for (int kb = kstart; kb <= qb; kb += 64) {
        for (int i = tid; i < 64 * 16; i += 128) {
            const int f = i * 4;
            *(float4*)(&Ks[f >> 6][f & 63]) = *(const float4*)(kg + (size_t)kb * HDIM + f);
            *(float4*)(&Vs[f >> 6][f & 63]) = *(const float4*)(vg + (size_t)kb * HDIM + f);
        }
        __syncthreads();

        for (int j = 0; j < 64; j++) {
            const int kj = kb + j;
            float s0 = 0.f, s1 = 0.f, s2 = 0.f, s3 = 0.f;
#pragma unroll
            for (int d = 0; d < 8; d++) {
                const float4 kk = *(const float4*)(&Ks[j][(d0 + d) * 4]);
                s0 += q4[d].x * kk.x;
                s1 += q4[d].y * kk.y;
                s2 += q4[d].z * kk.z;
                s3 += q4[d].w * kk.w;
            }
            float s = (s0 + s1) + (s2 + s3);
            s += __shfl_xor_sync(0xffffffffu, s, 1);   // full 64-dim dot

            if ((kj <= qi) && (kj + WIN >= qi)) {
                s *= 0.125f;
                if (s > m) {
                    const float alpha = __expf(m - s);
                    l *= alpha;
#pragma unroll
                    for (int d = 0; d < 8; d++) {
                        av[d].x *= alpha; av[d].y *= alpha;
                        av[d].z *= alpha; av[d].w *= alpha;
                    }
                    m = s;
                }
                const float p = __expf(s - m);
                l += p;
#pragma unroll
                for (int d = 0; d < 8; d++) {
                    const float4 vv = *(const float4*)(&Vs[j][(d0 + d) * 4]);
                    av[d].x += p * vv.x; av[d].y += p * vv.y;
                    av[d].z += p * vv.z; av[d].w += p * vv.w;
                }
            }
        }
        __syncthreads();
    }

    const float inv = 1.0f / l;
    float* og = g_attn + ((size_t)(b * SEQ + qi) * HN + h) * HDIM + half * 32;
#pragma unroll
    for (int d = 0; d < 8; d++) {
        float4 o = make_float4(av[d].x * inv, av[d].y * inv,
                               av[d].z * inv, av[d].w * inv);
        *(float4*)(og + d * 4) = o;
    }
}

// ---------------------------------------------------------------------------
extern "C" void kernel_launch(void* const* d_in, const int* in_sizes, int n_in,
                              void* d_out, int out_size)
{
    const float* hs = (const float*)d_in[0];
    const float* Wq = (const float*)d_in[1];
    const float* Wk = (const float*)d_in[2];
    const float* Wv = (const float*)d_in[3];
    const float* Wo = (const float*)d_in[4];
    float* out = (float*)d_out;

    float *qp, *kp, *vp, *ap;
    cudaGetSymbolAddress((void**)&qp, g_q);
    cudaGetSymbolAddress((void**)&kp, g_k);
    cudaGetSymbolAddress((void**)&vp, g_v);
    cudaGetSymbolAddress((void**)&ap, g_attn);

    const int M = BATCH * SEQ;   // 4096
    dim3 blk(256);

    build_rope_table<<<(SEQ * 32) / 256, 256>>>();

    // QKV projections (128x128 tiles, scatter into head layout)
    gemm128<1><<<dim3((HN * HDIM) / 128, M / 128), blk>>>(hs, Wq, qp, M, HN * HDIM, DM, HN);
    gemm128<1><<<dim3((KVN * HDIM) / 128, M / 128), blk>>>(hs, Wk, kp, M, KVN * HDIM, DM, KVN);
    gemm128<1><<<dim3((KVN * HDIM) / 128, M / 128), blk>>>(hs, Wv, vp, M, KVN * HDIM, DM, KVN);

    // RoPE from precomputed table
    rope_apply<<<(BATCH * HN * SEQ * 32) / 256, 256>>>(qp, BATCH * HN);
    rope_apply<<<(BATCH * KVN * SEQ * 32) / 256, 256>>>(kp, BATCH * KVN);

    // Attention
    attn_kernel<<<dim3(SEQ / 64, HN, BATCH), 128>>>();

    // Output projection
    gemm128<0><<<dim3(DM / 128, M / 128), blk>>>(ap, Wo, out, M, DM, DM, 0);
}

// round 8
// speedup vs baseline: 1.4133x; 1.4133x over previous
#include <cuda_runtime.h>
#include <math.h>
#include <stdint.h>

#define HN   16
#define KVN  8
#define HDIM 64
#define WIN  512
#define BATCH 2
#define SEQ  2048
#define DM   1024

// Scratch — layouts:
// g_q: [B, HN, S, 64], g_k/g_v: [B, KVN, S, 64], g_attn: [B*S, HN*64]
__device__ float g_q[(size_t)BATCH * HN * SEQ * HDIM];
__device__ float g_k[(size_t)BATCH * KVN * SEQ * HDIM];
__device__ float g_v[(size_t)BATCH * KVN * SEQ * HDIM];
__device__ float g_attn[(size_t)BATCH * SEQ * HN * HDIM];
// RoPE tables: [SEQ][32]
__device__ float g_cos[SEQ * 32];
__device__ float g_sin[SEQ * 32];

// ---------------------------------------------------------------------------
// RoPE table, double-precision trig (immune to --use_fast_math).
// ---------------------------------------------------------------------------
__global__ void build_rope_table()
{
    const int idx = blockIdx.x * blockDim.x + threadIdx.x;
    if (idx >= SEQ * 32) return;
    const int p = idx & 31;
    const int s = idx >> 5;
    const double invf = pow(10000.0, -((double)(2 * p)) / 64.0);
    const double ang = (double)s * invf;
    g_cos[idx] = (float)cos(ang);
    g_sin[idx] = (float)sin(ang);
}

__global__ void rope_apply(float* __restrict__ x, int rows)
{
    const int idx = blockIdx.x * blockDim.x + threadIdx.x;
    if (idx >= rows * SEQ * 32) return;
    const int p = idx & 31;
    const int s = (idx >> 5) & (SEQ - 1);

    const float c  = g_cos[(s << 5) | p];
    const float sn = g_sin[(s << 5) | p];

    float* base = x + (size_t)(idx >> 5) * HDIM;
    const float x1 = base[p];
    const float x2 = base[p + 32];
    base[p]      = x1 * c - x2 * sn;
    base[p + 32] = x2 * c + x1 * sn;
}

// ---------------------------------------------------------------------------
// tf32 tensor-core GEMM: C = A[M,K] @ B[K,N].
// BM=BN=128, BK=32, 256 threads = 8 warps; warp tile 64x32 via 4x4 fragments
// of mma.m16n8k8.tf32. tf32 rounding (cvt.rna) applied once at smem fill.
// As[m][k] pad 36 -> fragment banks 4r+c (conflict-free);
// Bs[k][n] pad 136 -> fragment banks 8c+r (conflict-free).
// MODE 0: linear row-major C. MODE 1: scatter to [B, NH, S, 64] head layout.
// ---------------------------------------------------------------------------
__device__ __forceinline__ uint32_t f2tf32(float f) {
    uint32_t u;
    asm("cvt.rna.tf32.f32 %0, %1;" : "=r"(u) : "f"(f));
    return u;
}

__device__ __forceinline__ void mma16n8k8(float* d, const uint32_t* a,
                                          const uint32_t* b) {
    asm("mma.sync.aligned.m16n8k8.row.col.f32.tf32.tf32.f32 "
        "{%0,%1,%2,%3}, {%4,%5,%6,%7}, {%8,%9}, {%0,%1,%2,%3};"
        : "+f"(d[0]), "+f"(d[1]), "+f"(d[2]), "+f"(d[3])
        : "r"(a[0]), "r"(a[1]), "r"(a[2]), "r"(a[3]),
          "r"(b[0]), "r"(b[1]));
}

template <int MODE>
__global__ void __launch_bounds__(256)
gemm_tc(const float* __restrict__ A, const float* __restrict__ Bm,
        float* __restrict__ C, int M, int N, int K, int NH)
{
    __shared__ uint32_t As[128][36];   // [m][k], tf32 bits
    __shared__ uint32_t Bs[32][136];   // [k][n], tf32 bits

    const int tid  = threadIdx.x;
    const int lane = tid & 31;
    const int wid  = tid >> 5;
    const int wy   = wid >> 2;          // 0..1 -> m offset wy*64
    const int wx   = wid & 3;           // 0..3 -> n offset wx*32
    const int r4   = lane >> 2;         // 0..7
    const int c4   = lane & 3;          // 0..3
    const int m0   = blockIdx.y * 128, n0 = blockIdx.x * 128;

    float acc[4][4][4] = {};

    for (int k0 = 0; k0 < K; k0 += 32) {
#pragma unroll
        for (int i0 = 0; i0 < 4; i0++) {
            const int i = tid + i0 * 256;            // 0..1023
            // A: row r (0..127), k cols c..c+3
            const int r = i >> 3, c = (i & 7) * 4;
            float4 av = *(const float4*)(A + (size_t)(m0 + r) * K + k0 + c);
            As[r][c + 0] = f2tf32(av.x); As[r][c + 1] = f2tf32(av.y);
            As[r][c + 2] = f2tf32(av.z); As[r][c + 3] = f2tf32(av.w);
            // B: k row br (0..31), n cols bc..bc+3
            const int br = i >> 5, bc = (i & 31) * 4;
            float4 bv = *(const float4*)(Bm + (size_t)(k0 + br) * N + n0 + bc);
            Bs[br][bc + 0] = f2tf32(bv.x); Bs[br][bc + 1] = f2tf32(bv.y);
            Bs[br][bc + 2] = f2tf32(bv.z); Bs[br][bc + 3] = f2tf32(bv.w);
        }
        __syncthreads();

#pragma unroll
        for (int kk = 0; kk < 32; kk += 8) {
            uint32_t af[4][4], bf[4][2];
#pragma unroll
            for (int mt = 0; mt < 4; mt++) {
                const int mb = wy * 64 + mt * 16;
                af[mt][0] = As[mb + r4    ][kk + c4    ];
                af[mt][1] = As[mb + r4 + 8][kk + c4    ];
                af[mt][2] = As[mb + r4    ][kk + c4 + 4];
                af[mt][3] = As[mb + r4 + 8][kk + c4 + 4];
            }
#pragma unroll
            for (int nt = 0; nt < 4; nt++) {
                const int nb = wx * 32 + nt * 8;
                bf[nt][0] = Bs[kk + c4    ][nb + r4];
                bf[nt][1] = Bs[kk + c4 + 4][nb + r4];
            }
#pragma unroll
            for (int mt = 0; mt < 4; mt++)
#pragma unroll
                for (int nt = 0; nt < 4; nt++)
                    mma16n8k8(acc[mt][nt], af[mt], bf[nt]);
        }
        __syncthreads();
    }

    // Epilogue: c0,c1 -> (row r4, cols 2c4,2c4+1); c2,c3 -> row r4+8.
#pragma unroll
    for (int mt = 0; mt < 4; mt++) {
#pragma unroll
        for (int nt = 0; nt < 4; nt++) {
            const int m = m0 + wy * 64 + mt * 16 + r4;
            const int n = n0 + wx * 32 + nt * 8 + 2 * c4;
#pragma unroll
            for (int half = 0; half < 2; half++) {
                const int mr = m + half * 8;
                float2 o = make_float2(acc[mt][nt][half * 2],
                                       acc[mt][nt][half * 2 + 1]);
                if (MODE == 0) {
                    *(float2*)(C + (size_t)mr * N + n) = o;
                } else {
                    const int b = mr / SEQ, s = mr % SEQ;
                    const int h = n >> 6, d = n & 63;
                    *(float2*)(C + (((size_t)(b * NH + h)) * SEQ + s) * HDIM + d) = o;
                }
            }
        }
    }
}

// ---------------------------------------------------------------------------
// Attention: 128 threads = one 64-query tile, 2 threads per query row.
// (validated in R7)
// ---------------------------------------------------------------------------
__global__ void __launch_bounds__(128) attn_kernel()
{
    __shared__ float Ks[64][68];
    __shared__ float Vs[64][68];

    const int b = blockIdx.z, h = blockIdx.y;
    const int qb = blockIdx.x * 64;
    const int kvh = h >> 1;            // n_rep = 2
    const int tid = threadIdx.x;
    const int row = tid >> 1;
    const int half = tid & 1;
    const int qi = qb + row;
    const int d0 = half * 8;

    const float* qg = g_q + ((size_t)(b * HN + h) * SEQ + qb) * HDIM;
    const float* kg = g_k + (size_t)(b * KVN + kvh) * SEQ * HDIM;
    const float* vg = g_v + (size_t)(b * KVN + kvh) * SEQ * HDIM;

    for (int i = tid; i < 64 * 16; i += 128) {
        const int f = i * 4;
        *(float4*)(&Ks[f >> 6][f & 63]) = *(const float4*)(qg + f);
    }
    __syncthreads();
    float4 q4[8];
#pragma unroll
    for (int d = 0; d < 8; d++) q4[d] = *(float4*)(&Ks[row][(d0 + d) * 4]);
    __syncthreads();

    float4 av[8];
#pragma unroll
    for (int d = 0; d < 8; d++) av[d] = make_float4(0.f, 0.f, 0.f, 0.f);
    float m = -1e30f, l = 0.0f;

    const int kstart = (qb >= WIN) ? (qb - WIN) : 0;

    for (int kb = kstart; kb <= qb; kb += 64) {
        for (int i = tid; i < 64 * 16; i += 128) {
            const int f = i * 4;
            *(float4*)(&Ks[f >> 6][f & 63]) = *(const float4*)(kg + (size_t)kb * HDIM + f);
            *(float4*)(&Vs[f >> 6][f & 63]) = *(const float4*)(vg + (size_t)kb * HDIM + f);
        }
        __syncthreads();

        for (int j = 0; j < 64; j++) {
            const int kj = kb + j;
            float s0 = 0.f, s1 = 0.f, s2 = 0.f, s3 = 0.f;
#pragma unroll
            for (int d = 0; d < 8; d++) {
                const float4 kk = *(const float4*)(&Ks[j][(d0 + d) * 4]);
                s0 += q4[d].x * kk.x;
                s1 += q4[d].y * kk.y;
                s2 += q4[d].z * kk.z;
                s3 += q4[d].w * kk.w;
            }
            float s = (s0 + s1) + (s2 + s3);
            s += __shfl_xor_sync(0xffffffffu, s, 1);

            if ((kj <= qi) && (kj + WIN >= qi)) {
                s *= 0.125f;
                if (s > m) {
                    const float alpha = __expf(m - s);
                    l *= alpha;
#pragma unroll
                    for (int d = 0; d < 8; d++) {
                        av[d].x *= alpha; av[d].y *= alpha;
                        av[d].z *= alpha; av[d].w *= alpha;
                    }
                    m = s;
                }
                const float p = __expf(s - m);
                l += p;
#pragma unroll
                for (int d = 0; d < 8; d++) {
                    const float4 vv = *(const float4*)(&Vs[j][(d0 + d) * 4]);
                    av[d].x += p * vv.x; av[d].y += p * vv.y;
                    av[d].z += p * vv.z; av[d].w += p * vv.w;
                }
            }
        }
        __syncthreads();
    }

    const float inv = 1.0f / l;
    float* og = g_attn + ((size_t)(b * SEQ + qi) * HN + h) * HDIM + half * 32;
#pragma unroll
    for (int d = 0; d < 8; d++) {
        float4 o = make_float4(av[d].x * inv, av[d].y * inv,
                               av[d].z * inv, av[d].w * inv);
        *(float4*)(og + d * 4) = o;
    }
}

// ---------------------------------------------------------------------------
extern "C" void kernel_launch(void* const* d_in, const int* in_sizes, int n_in,
                              void* d_out, int out_size)
{
    const float* hs = (const float*)d_in[0];
    const float* Wq = (const float*)d_in[1];
    const float* Wk = (const float*)d_in[2];
    const float* Wv = (const float*)d_in[3];
    const float* Wo = (const float*)d_in[4];
    float* out = (float*)d_out;

    float *qp, *kp, *vp, *ap;
    cudaGetSymbolAddress((void**)&qp, g_q);
    cudaGetSymbolAddress((void**)&kp, g_k);
    cudaGetSymbolAddress((void**)&vp, g_v);
    cudaGetSymbolAddress((void**)&ap, g_attn);

    const int M = BATCH * SEQ;   // 4096
    dim3 blk(256);

    build_rope_table<<<(SEQ * 32) / 256, 256>>>();

    // QKV projections (tf32 tensor-core GEMM, scatter into head layout)
    gemm_tc<1><<<dim3((HN * HDIM) / 128, M / 128), blk>>>(hs, Wq, qp, M, HN * HDIM, DM, HN);
    gemm_tc<1><<<dim3((KVN * HDIM) / 128, M / 128), blk>>>(hs, Wk, kp, M, KVN * HDIM, DM, KVN);
    gemm_tc<1><<<dim3((KVN * HDIM) / 128, M / 128), blk>>>(hs, Wv, vp, M, KVN * HDIM, DM, KVN);

    // RoPE from precomputed table
    rope_apply<<<(BATCH * HN * SEQ * 32) / 256, 256>>>(qp, BATCH * HN);
    rope_apply<<<(BATCH * KVN * SEQ * 32) / 256, 256>>>(kp, BATCH * KVN);

    // Attention (fp32)
    attn_kernel<<<dim3(SEQ / 64, HN, BATCH), 128>>>();

    // Output projection
    gemm_tc<0><<<dim3(DM / 128, M / 128), blk>>>(ap, Wo, out, M, DM, DM, 0);
}

// round 9
// speedup vs baseline: 3.0543x; 2.1611x over previous
#include <cuda_runtime.h>
#include <math.h>
#include <stdint.h>

#define HN   16
#define KVN  8
#define HDIM 64
#define WIN  512
#define BATCH 2
#define SEQ  2048
#define DM   1024

// Scratch — layouts:
// g_q: [B, HN, S, 64], g_k/g_v: [B, KVN, S, 64], g_attn: [B*S, HN*64]
__device__ float g_q[(size_t)BATCH * HN * SEQ * HDIM];
__device__ float g_k[(size_t)BATCH * KVN * SEQ * HDIM];
__device__ float g_v[(size_t)BATCH * KVN * SEQ * HDIM];
__device__ float g_attn[(size_t)BATCH * SEQ * HN * HDIM];
// RoPE tables: [SEQ][32]
__device__ float g_cos[SEQ * 32];
__device__ float g_sin[SEQ * 32];

// ---------------------------------------------------------------------------
// RoPE table, double-precision trig (immune to --use_fast_math).
// ---------------------------------------------------------------------------
__global__ void build_rope_table()
{
    const int idx = blockIdx.x * blockDim.x + threadIdx.x;
    if (idx >= SEQ * 32) return;
    const int p = idx & 31;
    const int s = idx >> 5;
    const double invf = pow(10000.0, -((double)(2 * p)) / 64.0);
    const double ang = (double)s * invf;
    g_cos[idx] = (float)cos(ang);
    g_sin[idx] = (float)sin(ang);
}

__global__ void rope_apply(float* __restrict__ x, int rows)
{
    const int idx = blockIdx.x * blockDim.x + threadIdx.x;
    if (idx >= rows * SEQ * 32) return;
    const int p = idx & 31;
    const int s = (idx >> 5) & (SEQ - 1);

    const float c  = g_cos[(s << 5) | p];
    const float sn = g_sin[(s << 5) | p];

    float* base = x + (size_t)(idx >> 5) * HDIM;
    const float x1 = base[p];
    const float x2 = base[p + 32];
    base[p]      = x1 * c - x2 * sn;
    base[p + 32] = x2 * c + x1 * sn;
}

// ---------------------------------------------------------------------------
// tf32 helpers (validated in R8)
// ---------------------------------------------------------------------------
__device__ __forceinline__ uint32_t f2tf32(float f) {
    uint32_t u;
    asm("cvt.rna.tf32.f32 %0, %1;" : "=r"(u) : "f"(f));
    return u;
}

__device__ __forceinline__ void mma16n8k8(float* d, const uint32_t* a,
                                          const uint32_t* b) {
    asm("mma.sync.aligned.m16n8k8.row.col.f32.tf32.tf32.f32 "
        "{%0,%1,%2,%3}, {%4,%5,%6,%7}, {%8,%9}, {%0,%1,%2,%3};"
        : "+f"(d[0]), "+f"(d[1]), "+f"(d[2]), "+f"(d[3])
        : "r"(a[0]), "r"(a[1]), "r"(a[2]), "r"(a[3]),
          "r"(b[0]), "r"(b[1]));
}

// ---------------------------------------------------------------------------
// tf32 tensor-core GEMM (validated in R8): C = A[M,K] @ B[K,N].
// BM=BN=128, BK=32, 256 threads = 8 warps; warp tile 64x32.
// MODE 0: linear C. MODE 1: scatter to [B, NH, S, 64] head layout.
// ---------------------------------------------------------------------------
template <int MODE>
__global__ void __launch_bounds__(256)
gemm_tc(const float* __restrict__ A, const float* __restrict__ Bm,
        float* __restrict__ C, int M, int N, int K, int NH)
{
    __shared__ uint32_t As[128][36];
    __shared__ uint32_t Bs[32][136];

    const int tid  = threadIdx.x;
    const int lane = tid & 31;
    const int wid  = tid >> 5;
    const int wy   = wid >> 2;
    const int wx   = wid & 3;
    const int r4   = lane >> 2;
    const int c4   = lane & 3;
    const int m0   = blockIdx.y * 128, n0 = blockIdx.x * 128;

    float acc[4][4][4] = {};

    for (int k0 = 0; k0 < K; k0 += 32) {
#pragma unroll
        for (int i0 = 0; i0 < 4; i0++) {
            const int i = tid + i0 * 256;
            const int r = i >> 3, c = (i & 7) * 4;
            float4 av = *(const float4*)(A + (size_t)(m0 + r) * K + k0 + c);
            As[r][c + 0] = f2tf32(av.x); As[r][c + 1] = f2tf32(av.y);
            As[r][c + 2] = f2tf32(av.z); As[r][c + 3] = f2tf32(av.w);
            const int br = i >> 5, bc = (i & 31) * 4;
            float4 bv = *(const float4*)(Bm + (size_t)(k0 + br) * N + n0 + bc);
            Bs[br][bc + 0] = f2tf32(bv.x); Bs[br][bc + 1] = f2tf32(bv.y);
            Bs[br][bc + 2] = f2tf32(bv.z); Bs[br][bc + 3] = f2tf32(bv.w);
        }
        __syncthreads();

#pragma unroll
        for (int kk = 0; kk < 32; kk += 8) {
            uint32_t af[4][4], bf[4][2];
#pragma unroll
            for (int mt = 0; mt < 4; mt++) {
                const int mb = wy * 64 + mt * 16;
                af[mt][0] = As[mb + r4    ][kk + c4    ];
                af[mt][1] = As[mb + r4 + 8][kk + c4    ];
                af[mt][2] = As[mb + r4    ][kk + c4 + 4];
                af[mt][3] = As[mb + r4 + 8][kk + c4 + 4];
            }
#pragma unroll
            for (int nt = 0; nt < 4; nt++) {
                const int nb = wx * 32 + nt * 8;
                bf[nt][0] = Bs[kk + c4    ][nb + r4];
                bf[nt][1] = Bs[kk + c4 + 4][nb + r4];
            }
#pragma unroll
            for (int mt = 0; mt < 4; mt++)
#pragma unroll
                for (int nt = 0; nt < 4; nt++)
                    mma16n8k8(acc[mt][nt], af[mt], bf[nt]);
        }
        __syncthreads();
    }

#pragma unroll
    for (int mt = 0; mt < 4; mt++) {
#pragma unroll
        for (int nt = 0; nt < 4; nt++) {
            const int m = m0 + wy * 64 + mt * 16 + r4;
            const int n = n0 + wx * 32 + nt * 8 + 2 * c4;
#pragma unroll
            for (int half = 0; half < 2; half++) {
                const int mr = m + half * 8;
                float2 o = make_float2(acc[mt][nt][half * 2],
                                       acc[mt][nt][half * 2 + 1]);
                if (MODE == 0) {
                    *(float2*)(C + (size_t)mr * N + n) = o;
                } else {
                    const int b = mr / SEQ, s = mr % SEQ;
                    const int h = n >> 6, d = n & 63;
                    *(float2*)(C + (((size_t)(b * NH + h)) * SEQ + s) * HDIM + d) = o;
                }
            }
        }
    }
}

// ---------------------------------------------------------------------------
// MMA flash attention: 128 threads = 4 warps = one 64-query tile; each warp
// owns 16 query rows. S = Q@K^T and O += P@V on tensor cores (tf32); softmax
// in fp32, row state held redundantly by each 4-lane c4 group.
// Smem (tf32 bits, stride 72 words -> conflict-free fragment reads):
//   Ps[64][72] (Q staging, then P), Ks[64][72], Vs[64][72]  = 54 KB dynamic.
// ---------------------------------------------------------------------------
#define ATS 72
#define ATTN_SMEM_BYTES (3 * 64 * ATS * 4)

__global__ void __launch_bounds__(128) attn_mma()
{
    extern __shared__ uint32_t smu[];
    uint32_t (*Ps)[ATS] = (uint32_t(*)[ATS])(smu);
    uint32_t (*Ks)[ATS] = (uint32_t(*)[ATS])(smu + 64 * ATS);
    uint32_t (*Vs)[ATS] = (uint32_t(*)[ATS])(smu + 2 * 64 * ATS);

    const int b = blockIdx.z, h = blockIdx.y;
    const int qb = blockIdx.x * 64;
    const int kvh = h >> 1;            // n_rep = 2
    const int tid  = threadIdx.x;
    const int lane = tid & 31;
    const int wid  = tid >> 5;         // 0..3
    const int mb   = wid * 16;         // warp's query-row base
    const int r4   = lane >> 2;        // 0..7
    const int c4   = lane & 3;         // 0..3

    const float* qg = g_q + ((size_t)(b * HN + h) * SEQ + qb) * HDIM;
    const float* kg = g_k + (size_t)(b * KVN + kvh) * SEQ * HDIM;
    const float* vg = g_v + (size_t)(b * KVN + kvh) * SEQ * HDIM;

    // Stage Q (pre-scaled by 1/sqrt(64)) into Ps as tf32.
    for (int i = tid; i < 64 * 16; i += 128) {
        const int f = i * 4;
        const int row = f >> 6, col = f & 63;
        float4 v = *(const float4*)(qg + f);
        Ps[row][col + 0] = f2tf32(v.x * 0.125f);
        Ps[row][col + 1] = f2tf32(v.y * 0.125f);
        Ps[row][col + 2] = f2tf32(v.z * 0.125f);
        Ps[row][col + 3] = f2tf32(v.w * 0.125f);
    }
    __syncthreads();

    // Q fragments: aq[ks] covers k-dims ks*8..ks*8+7 for rows mb+r4, mb+r4+8.
    uint32_t aq[8][4];
#pragma unroll
    for (int ks = 0; ks < 8; ks++) {
        aq[ks][0] = Ps[mb + r4    ][ks * 8 + c4    ];
        aq[ks][1] = Ps[mb + r4 + 8][ks * 8 + c4    ];
        aq[ks][2] = Ps[mb + r4    ][ks * 8 + c4 + 4];
        aq[ks][3] = Ps[mb + r4 + 8][ks * 8 + c4 + 4];
    }

    float oacc[8][4] = {};
    float m2[2] = {-1e30f, -1e30f};
    float l2[2] = {0.0f, 0.0f};
    const int qi0 = qb + mb + r4;      // row of c0,c1
    const int qi1 = qi0 + 8;           // row of c2,c3

    const int kstart = (qb >= WIN) ? (qb - WIN) : 0;

    for (int kb = kstart; kb <= qb; kb += 64) {
        __syncthreads();   // previous tile's consumers done (also covers Q staging reuse)
        for (int i = tid; i < 64 * 16; i += 128) {
            const int f = i * 4;
            const int row = f >> 6, col = f & 63;
            float4 kv = *(const float4*)(kg + (size_t)kb * HDIM + f);
            Ks[row][col + 0] = f2tf32(kv.x); Ks[row][col + 1] = f2tf32(kv.y);
            Ks[row][col + 2] = f2tf32(kv.z); Ks[row][col + 3] = f2tf32(kv.w);
            float4 vv = *(const float4*)(vg + (size_t)kb * HDIM + f);
            Vs[row][col + 0] = f2tf32(vv.x); Vs[row][col + 1] = f2tf32(vv.y);
            Vs[row][col + 2] = f2tf32(vv.z); Vs[row][col + 3] = f2tf32(vv.w);
        }
        __syncthreads();

        // ---- S = Q @ K^T : sacc[nt] = 16x8 tile over keys kb+nt*8.. ----
        float sacc[8][4] = {};
#pragma unroll
        for (int ks = 0; ks < 8; ks++) {
#pragma unroll
            for (int nt = 0; nt < 8; nt++) {
                uint32_t bk[2];
                bk[0] = Ks[nt * 8 + r4][ks * 8 + c4    ];
                bk[1] = Ks[nt * 8 + r4][ks * 8 + c4 + 4];
                mma16n8k8(sacc[nt], aq[ks], bk);
            }
        }

        // ---- mask + row max ----
        float rmax0 = -1e30f, rmax1 = -1e30f;
#pragma unroll
        for (int nt = 0; nt < 8; nt++) {
            const int kj = kb + nt * 8 + 2 * c4;
            // row qi0 (c0: col kj, c1: col kj+1)
            if (!((kj     <= qi0) && (kj     + WIN >= qi0))) sacc[nt][0] = -1e30f;
            if (!((kj + 1 <= qi0) && (kj + 1 + WIN >= qi0))) sacc[nt][1] = -1e30f;
            if (!((kj     <= qi1) && (kj     + WIN >= qi1))) sacc[nt][2] = -1e30f;
            if (!((kj + 1 <= qi1) && (kj + 1 + WIN >= qi1))) sacc[nt][3] = -1e30f;
            rmax0 = fmaxf(rmax0, fmaxf(sacc[nt][0], sacc[nt][1]));
            rmax1 = fmaxf(rmax1, fmaxf(sacc[nt][2], sacc[nt][3]));
        }
        rmax0 = fmaxf(rmax0, __shfl_xor_sync(0xffffffffu, rmax0, 1));
        rmax0 = fmaxf(rmax0, __shfl_xor_sync(0xffffffffu, rmax0, 2));
        rmax1 = fmaxf(rmax1, __shfl_xor_sync(0xffffffffu, rmax1, 1));
        rmax1 = fmaxf(rmax1, __shfl_xor_sync(0xffffffffu, rmax1, 2));

        const float mn0 = fmaxf(m2[0], rmax0);
        const float mn1 = fmaxf(m2[1], rmax1);
        const float al0 = __expf(m2[0] - mn0);
        const float al1 = __expf(m2[1] - mn1);
        m2[0] = mn0; m2[1] = mn1;

        // ---- P = exp(S - m), store to Ps (tf32), row sums ----
        float rs0 = 0.f, rs1 = 0.f;
#pragma unroll
        for (int nt = 0; nt < 8; nt++) {
            const float p0 = __expf(sacc[nt][0] - mn0);
            const float p1 = __expf(sacc[nt][1] - mn0);
            const float p2 = __expf(sacc[nt][2] - mn1);
            const float p3 = __expf(sacc[nt][3] - mn1);
            rs0 += p0 + p1; rs1 += p2 + p3;
            uint2 u01 = make_uint2(f2tf32(p0), f2tf32(p1));
            uint2 u23 = make_uint2(f2tf32(p2), f2tf32(p3));
            *(uint2*)(&Ps[mb + r4    ][nt * 8 + 2 * c4]) = u01;
            *(uint2*)(&Ps[mb + r4 + 8][nt * 8 + 2 * c4]) = u23;
        }
        rs0 += __shfl_xor_sync(0xffffffffu, rs0, 1);
        rs0 += __shfl_xor_sync(0xffffffffu, rs0, 2);
        rs1 += __shfl_xor_sync(0xffffffffu, rs1, 1);
        rs1 += __shfl_xor_sync(0xffffffffu, rs1, 2);
        l2[0] = l2[0] * al0 + rs0;
        l2[1] = l2[1] * al1 + rs1;

#pragma unroll
        for (int dt = 0; dt < 8; dt++) {
            oacc[dt][0] *= al0; oacc[dt][1] *= al0;
            oacc[dt][2] *= al1; oacc[dt][3] *= al1;
        }
        __syncwarp();   // P stores visible to fragment loads within the warp

        // ---- O += P @ V ----
#pragma unroll
        for (int ks = 0; ks < 8; ks++) {
            uint32_t ap[4];
            ap[0] = Ps[mb + r4    ][ks * 8 + c4    ];
            ap[1] = Ps[mb + r4 + 8][ks * 8 + c4    ];
            ap[2] = Ps[mb + r4    ][ks * 8 + c4 + 4];
            ap[3] = Ps[mb + r4 + 8][ks * 8 + c4 + 4];
#pragma unroll
            for (int dt = 0; dt < 8; dt++) {
                uint32_t bv[2];
                bv[0] = Vs[ks * 8 + c4    ][dt * 8 + r4];
                bv[1] = Vs[ks * 8 + c4 + 4][dt * 8 + r4];
                mma16n8k8(oacc[dt], ap, bv);
            }
        }
    }

    // ---- epilogue: normalize, write [B*S, HN*64] ----
    const float inv0 = 1.0f / l2[0];
    const float inv1 = 1.0f / l2[1];
#pragma unroll
    for (int dt = 0; dt < 8; dt++) {
        const int d = dt * 8 + 2 * c4;
        float* o0 = g_attn + ((size_t)(b * SEQ + qi0) * HN + h) * HDIM + d;
        float* o1 = g_attn + ((size_t)(b * SEQ + qi1) * HN + h) * HDIM + d;
        *(float2*)o0 = make_float2(oacc[dt][0] * inv0, oacc[dt][1] * inv0);
        *(float2*)o1 = make_float2(oacc[dt][2] * inv1, oacc[dt][3] * inv1);
    }
}

// ---------------------------------------------------------------------------
extern "C" void kernel_launch(void* const* d_in, const int* in_sizes, int n_in,
                              void* d_out, int out_size)
{
    const float* hs = (const float*)d_in[0];
    const float* Wq = (const float*)d_in[1];
    const float* Wk = (const float*)d_in[2];
    const float* Wv = (const float*)d_in[3];
    const float* Wo = (const float*)d_in[4];
    float* out = (float*)d_out;

    float *qp, *kp, *vp, *ap;
    cudaGetSymbolAddress((void**)&qp, g_q);
    cudaGetSymbolAddress((void**)&kp, g_k);
    cudaGetSymbolAddress((void**)&vp, g_v);
    cudaGetSymbolAddress((void**)&ap, g_attn);

    const int M = BATCH * SEQ;   // 4096
    dim3 blk(256);

    build_rope_table<<<(SEQ * 32) / 256, 256>>>();

    // QKV projections (tf32 tensor-core GEMM, scatter into head layout)
    gemm_tc<1><<<dim3((HN * HDIM) / 128, M / 128), blk>>>(hs, Wq, qp, M, HN * HDIM, DM, HN);
    gemm_tc<1><<<dim3((KVN * HDIM) / 128, M / 128), blk>>>(hs, Wk, kp, M, KVN * HDIM, DM, KVN);
    gemm_tc<1><<<dim3((KVN * HDIM) / 128, M / 128), blk>>>(hs, Wv, vp, M, KVN * HDIM, DM, KVN);

    // RoPE from precomputed table
    rope_apply<<<(BATCH * HN * SEQ * 32) / 256, 256>>>(qp, BATCH * HN);
    rope_apply<<<(BATCH * KVN * SEQ * 32) / 256, 256>>>(kp, BATCH * KVN);

    // Attention (tf32 MMA flash)
    cudaFuncSetAttribute(attn_mma,
                         cudaFuncAttributeMaxDynamicSharedMemorySize,
                         ATTN_SMEM_BYTES);
    attn_mma<<<dim3(SEQ / 64, HN, BATCH), 128, ATTN_SMEM_BYTES>>>();

    // Output projection
    gemm_tc<0><<<dim3(DM / 128, M / 128), blk>>>(ap, Wo, out, M, DM, DM, 0);
}

// round 10
// speedup vs baseline: 3.5558x; 1.1642x over previous
#include <cuda_runtime.h>
#include <math.h>
#include <stdint.h>

#define HN   16
#define KVN  8
#define HDIM 64
#define WIN  512
#define BATCH 2
#define SEQ  2048
#define DM   1024

// Scratch — layouts:
// g_q: [B, HN, S, 64], g_k/g_v: [B, KVN, S, 64], g_attn: [B*S, HN*64]
__device__ float g_q[(size_t)BATCH * HN * SEQ * HDIM];
__device__ float g_k[(size_t)BATCH * KVN * SEQ * HDIM];
__device__ float g_v[(size_t)BATCH * KVN * SEQ * HDIM];
__device__ float g_attn[(size_t)BATCH * SEQ * HN * HDIM];
// RoPE tables: [SEQ][32]
__device__ float g_cos[SEQ * 32];
__device__ float g_sin[SEQ * 32];

// ---------------------------------------------------------------------------
// RoPE table, double-precision trig (immune to --use_fast_math).
// ---------------------------------------------------------------------------
__global__ void build_rope_table()
{
    const int idx = blockIdx.x * blockDim.x + threadIdx.x;
    if (idx >= SEQ * 32) return;
    const int p = idx & 31;
    const int s = idx >> 5;
    const double invf = pow(10000.0, -((double)(2 * p)) / 64.0);
    const double ang = (double)s * invf;
    g_cos[idx] = (float)cos(ang);
    g_sin[idx] = (float)sin(ang);
}

__global__ void rope_apply(float* __restrict__ x, int rows)
{
    const int idx = blockIdx.x * blockDim.x + threadIdx.x;
    if (idx >= rows * SEQ * 32) return;
    const int p = idx & 31;
    const int s = (idx >> 5) & (SEQ - 1);

    const float c  = g_cos[(s << 5) | p];
    const float sn = g_sin[(s << 5) | p];

    float* base = x + (size_t)(idx >> 5) * HDIM;
    const float x1 = base[p];
    const float x2 = base[p + 32];
    base[p]      = x1 * c - x2 * sn;
    base[p + 32] = x2 * c + x1 * sn;
}

// ---------------------------------------------------------------------------
// tf32 helpers (validated R8/R9)
// ---------------------------------------------------------------------------
__device__ __forceinline__ uint32_t f2tf32(float f) {
    uint32_t u;
    asm("cvt.rna.tf32.f32 %0, %1;" : "=r"(u) : "f"(f));
    return u;
}

__device__ __forceinline__ void mma16n8k8(float* d, const uint32_t* a,
                                          const uint32_t* b) {
    asm("mma.sync.aligned.m16n8k8.row.col.f32.tf32.tf32.f32 "
        "{%0,%1,%2,%3}, {%4,%5,%6,%7}, {%8,%9}, {%0,%1,%2,%3};"
        : "+f"(d[0]), "+f"(d[1]), "+f"(d[2]), "+f"(d[3])
        : "r"(a[0]), "r"(a[1]), "r"(a[2]), "r"(a[3]),
          "r"(b[0]), "r"(b[1]));
}

#define CP_ASYNC16(dst_u32, src_ptr) \
    asm volatile("cp.async.ca.shared.global [%0], [%1], 16;" \
                 :: "r"(dst_u32), "l"(src_ptr))
#define CP_COMMIT() asm volatile("cp.async.commit_group;")
#define CP_WAIT(n)  asm volatile("cp.async.wait_group %0;" :: "n"(n))

// ---------------------------------------------------------------------------
// cp.async double-buffered tf32 GEMM body. C = A[M,K] @ B[K,N].
// BM=BN=128, BK=16, 256 threads = 8 warps, warp tile 64x32.
// Smem holds raw fp32 (cp.async); cvt to tf32 at fragment load (ALU is idle).
// As[2][128][20]: fragment banks r4*20+c4 -> all-32-distinct (conflict-free).
// Bs[2][16][136]: fragment banks 8*c4+r4 pattern (validated R8).
// MODE 0: linear row-major C. MODE 1: scatter to [B, NH, S, 64] head layout.
// ---------------------------------------------------------------------------
template <int MODE>
__device__ __forceinline__ void gemm_body(
    const float* __restrict__ A, const float* __restrict__ Bm,
    float* __restrict__ C, int M, int N, int K, int NH)
{
    __shared__ float As[2][128][20];
    __shared__ float Bs[2][16][136];

    const int tid  = threadIdx.x;
    const int lane = tid & 31;
    const int wid  = tid >> 5;
    const int wy   = wid >> 2;
    const int wx   = wid & 3;
    const int r4   = lane >> 2;
    const int c4   = lane & 3;
    const int m0   = blockIdx.y * 128, n0 = blockIdx.x * 128;

    const int NT = K / 16;

    // -- prologue: load tile 0 into buffer 0 --
    {
#pragma unroll
        for (int i0 = 0; i0 < 2; i0++) {
            const int i = tid + i0 * 256;
            const int r = i >> 2, c = (i & 3) * 4;
            CP_ASYNC16((uint32_t)__cvta_generic_to_shared(&As[0][r][c]),
                       A + (size_t)(m0 + r) * K + c);
            const int br = i >> 5, bc = (i & 31) * 4;
            CP_ASYNC16((uint32_t)__cvta_generic_to_shared(&Bs[0][br][bc]),
                       Bm + (size_t)br * N + n0 + bc);
        }
        CP_COMMIT();
    }

    float acc[4][4][4] = {};
    int buf = 0;

    for (int kt = 0; kt < NT; kt++) {
        if (kt + 1 < NT) {
            const int k0 = (kt + 1) * 16;
            const int nb = buf ^ 1;
#pragma unroll
            for (int i0 = 0; i0 < 2; i0++) {
                const int i = tid + i0 * 256;
                const int r = i >> 2, c = (i & 3) * 4;
                CP_ASYNC16((uint32_t)__cvta_generic_to_shared(&As[nb][r][c]),
                           A + (size_t)(m0 + r) * K + k0 + c);
                const int br = i >> 5, bc = (i & 31) * 4;
                CP_ASYNC16((uint32_t)__cvta_generic_to_shared(&Bs[nb][br][bc]),
                           Bm + (size_t)(k0 + br) * N + n0 + bc);
            }
            CP_COMMIT();
            CP_WAIT(1);          // current buf's group complete
        } else {
            CP_WAIT(0);
        }
        __syncthreads();

#pragma unroll
        for (int kk = 0; kk < 16; kk += 8) {
            uint32_t af[4][4], bf[4][2];
#pragma unroll
            for (int mt = 0; mt < 4; mt++) {
                const int mb = wy * 64 + mt * 16;
                af[mt][0] = f2tf32(As[buf][mb + r4    ][kk + c4    ]);
                af[mt][1] = f2tf32(As[buf][mb + r4 + 8][kk + c4    ]);
                af[mt][2] = f2tf32(As[buf][mb + r4    ][kk + c4 + 4]);
                af[mt][3] = f2tf32(As[buf][mb + r4 + 8][kk + c4 + 4]);
            }
#pragma unroll
            for (int nt = 0; nt < 4; nt++) {
                const int nb2 = wx * 32 + nt * 8;
                bf[nt][0] = f2tf32(Bs[buf][kk + c4    ][nb2 + r4]);
                bf[nt][1] = f2tf32(Bs[buf][kk + c4 + 4][nb2 + r4]);
            }
#pragma unroll
            for (int mt = 0; mt < 4; mt++)
#pragma unroll
                for (int nt = 0; nt < 4; nt++)
                    mma16n8k8(acc[mt][nt], af[mt], bf[nt]);
        }
        __syncthreads();         // compute done before next iter overwrites buf
        buf ^= 1;
    }

#pragma unroll
    for (int mt = 0; mt < 4; mt++) {
#pragma unroll
        for (int nt = 0; nt < 4; nt++) {
            const int m = m0 + wy * 64 + mt * 16 + r4;
            const int n = n0 + wx * 32 + nt * 8 + 2 * c4;
#pragma unroll
            for (int half = 0; half < 2; half++) {
                const int mr = m + half * 8;
                float2 o = make_float2(acc[mt][nt][half * 2],
                                       acc[mt][nt][half * 2 + 1]);
                if (MODE == 0) {
                    *(float2*)(C + (size_t)mr * N + n) = o;
                } else {
                    const int b = mr / SEQ, s = mr % SEQ;
                    const int h = n >> 6, d = n & 63;
                    *(float2*)(C + (((size_t)(b * NH + h)) * SEQ + s) * HDIM + d) = o;
                }
            }
        }
    }
}

// Fused QKV projection: blockIdx.z selects {Wq->g_q, Wk->g_k, Wv->g_v}.
__global__ void __launch_bounds__(256, 2)
gemm_qkv(const float* __restrict__ hs,
         const float* __restrict__ Wq, const float* __restrict__ Wk,
         const float* __restrict__ Wv,
         float* __restrict__ qp, float* __restrict__ kp, float* __restrict__ vp)
{
    const int z = blockIdx.z;
    const float* Bm; float* C; int N, NH;
    if (z == 0)      { Bm = Wq; C = qp; N = HN  * HDIM; NH = HN;  }
    else if (z == 1) { Bm = Wk; C = kp; N = KVN * HDIM; NH = KVN; }
    else             { Bm = Wv; C = vp; N = KVN * HDIM; NH = KVN; }
    if (blockIdx.x * 128 >= N) return;   // uniform per block
    gemm_body<1>(hs, Bm, C, BATCH * SEQ, N, DM, NH);
}

__global__ void __launch_bounds__(256, 2)
gemm_out(const float* __restrict__ A, const float* __restrict__ Bm,
         float* __restrict__ C)
{
    gemm_body<0>(A, Bm, C, BATCH * SEQ, DM, DM, 0);
}

// ---------------------------------------------------------------------------
// MMA flash attention (validated R9): 128 threads = 4 warps, 64-query tile.
// ---------------------------------------------------------------------------
#define ATS 72
#define ATTN_SMEM_BYTES (3 * 64 * ATS * 4)

__global__ void __launch_bounds__(128) attn_mma()
{
    extern __shared__ uint32_t smu[];
    uint32_t (*Ps)[ATS] = (uint32_t(*)[ATS])(smu);
    uint32_t (*Ks)[ATS] = (uint32_t(*)[ATS])(smu + 64 * ATS);
    uint32_t (*Vs)[ATS] = (uint32_t(*)[ATS])(smu + 2 * 64 * ATS);

    const int b = blockIdx.z, h = blockIdx.y;
    const int qb = blockIdx.x * 64;
    const int kvh = h >> 1;            // n_rep = 2
    const int tid  = threadIdx.x;
    const int lane = tid & 31;
    const int wid  = tid >> 5;
    const int mb   = wid * 16;
    const int r4   = lane >> 2;
    const int c4   = lane & 3;

    const float* qg = g_q + ((size_t)(b * HN + h) * SEQ + qb) * HDIM;
    const float* kg = g_k + (size_t)(b * KVN + kvh) * SEQ * HDIM;
    const float* vg = g_v + (size_t)(b * KVN + kvh) * SEQ * HDIM;

    for (int i = tid; i < 64 * 16; i += 128) {
        const int f = i * 4;
        const int row = f >> 6, col = f & 63;
        float4 v = *(const float4*)(qg + f);
        Ps[row][col + 0] = f2tf32(v.x * 0.125f);
        Ps[row][col + 1] = f2tf32(v.y * 0.125f);
        Ps[row][col + 2] = f2tf32(v.z * 0.125f);
        Ps[row][col + 3] = f2tf32(v.w * 0.125f);
    }
    __syncthreads();

    uint32_t aq[8][4];
#pragma unroll
    for (int ks = 0; ks < 8; ks++) {
        aq[ks][0] = Ps[mb + r4    ][ks * 8 + c4    ];
        aq[ks][1] = Ps[mb + r4 + 8][ks * 8 + c4    ];
        aq[ks][2] = Ps[mb + r4    ][ks * 8 + c4 + 4];
        aq[ks][3] = Ps[mb + r4 + 8][ks * 8 + c4 + 4];
    }

    float oacc[8][4] = {};
    float m2[2] = {-1e30f, -1e30f};
    float l2[2] = {0.0f, 0.0f};
    const int qi0 = qb + mb + r4;
    const int qi1 = qi0 + 8;

    const int kstart = (qb >= WIN) ? (qb - WIN) : 0;

    for (int kb = kstart; kb <= qb; kb += 64) {
        __syncthreads();
        for (int i = tid; i < 64 * 16; i += 128) {
            const int f = i * 4;
            const int row = f >> 6, col = f & 63;
            float4 kv = *(const float4*)(kg + (size_t)kb * HDIM + f);
            Ks[row][col + 0] = f2tf32(kv.x); Ks[row][col + 1] = f2tf32(kv.y);
            Ks[row][col + 2] = f2tf32(kv.z); Ks[row][col + 3] = f2tf32(kv.w);
            float4 vv = *(const float4*)(vg + (size_t)kb * HDIM + f);
            Vs[row][col + 0] = f2tf32(vv.x); Vs[row][col + 1] = f2tf32(vv.y);
            Vs[row][col + 2] = f2tf32(vv.z); Vs[row][col + 3] = f2tf32(vv.w);
        }
        __syncthreads();

        float sacc[8][4] = {};
#pragma unroll
        for (int ks = 0; ks < 8; ks++) {
#pragma unroll
            for (int nt = 0; nt < 8; nt++) {
                uint32_t bk[2];
                bk[0] = Ks[nt * 8 + r4][ks * 8 + c4    ];
                bk[1] = Ks[nt * 8 + r4][ks * 8 + c4 + 4];
                mma16n8k8(sacc[nt], aq[ks], bk);
            }
        }

        float rmax0 = -1e30f, rmax1 = -1e30f;
#pragma unroll
        for (int nt = 0; nt < 8; nt++) {
            const int kj = kb + nt * 8 + 2 * c4;
            if (!((kj     <= qi0) && (kj     + WIN >= qi0))) sacc[nt][0] = -1e30f;
            if (!((kj + 1 <= qi0) && (kj + 1 + WIN >= qi0))) sacc[nt][1] = -1e30f;
            if (!((kj     <= qi1) && (kj     + WIN >= qi1))) sacc[nt][2] = -1e30f;
            if (!((kj + 1 <= qi1) && (kj + 1 + WIN >= qi1))) sacc[nt][3] = -1e30f;
            rmax0 = fmaxf(rmax0, fmaxf(sacc[nt][0], sacc[nt][1]));
            rmax1 = fmaxf(rmax1, fmaxf(sacc[nt][2], sacc[nt][3]));
        }
        rmax0 = fmaxf(rmax0, __shfl_xor_sync(0xffffffffu, rmax0, 1));
        rmax0 = fmaxf(rmax0, __shfl_xor_sync(0xffffffffu, rmax0, 2));
        rmax1 = fmaxf(rmax1, __shfl_xor_sync(0xffffffffu, rmax1, 1));
        rmax1 = fmaxf(rmax1, __shfl_xor_sync(0xffffffffu, rmax1, 2));

        const float mn0 = fmaxf(m2[0], rmax0);
        const float mn1 = fmaxf(m2[1], rmax1);
        const float al0 = __expf(m2[0] - mn0);
        const float al1 = __expf(m2[1] - mn1);
        m2[0] = mn0; m2[1] = mn1;

        float rs0 = 0.f, rs1 = 0.f;
#pragma unroll
        for (int nt = 0; nt < 8; nt++) {
            const float p0 = __expf(sacc[nt][0] - mn0);
            const float p1 = __expf(sacc[nt][1] - mn0);
            const float p2 = __expf(sacc[nt][2] - mn1);
            const float p3 = __expf(sacc[nt][3] - mn1);
            rs0 += p0 + p1; rs1 += p2 + p3;
            uint2 u01 = make_uint2(f2tf32(p0), f2tf32(p1));
            uint2 u23 = make_uint2(f2tf32(p2), f2tf32(p3));
            *(uint2*)(&Ps[mb + r4    ][nt * 8 + 2 * c4]) = u01;
            *(uint2*)(&Ps[mb + r4 + 8][nt * 8 + 2 * c4]) = u23;
        }
        rs0 += __shfl_xor_sync(0xffffffffu, rs0, 1);
        rs0 += __shfl_xor_sync(0xffffffffu, rs0, 2);
        rs1 += __shfl_xor_sync(0xffffffffu, rs1, 1);
        rs1 += __shfl_xor_sync(0xffffffffu, rs1, 2);
        l2[0] = l2[0] * al0 + rs0;
        l2[1] = l2[1] * al1 + rs1;

#pragma unroll
        for (int dt = 0; dt < 8; dt++) {
            oacc[dt][0] *= al0; oacc[dt][1] *= al0;
            oacc[dt][2] *= al1; oacc[dt][3] *= al1;
        }
        __syncwarp();

#pragma unroll
        for (int ks = 0; ks < 8; ks++) {
            uint32_t ap[4];
            ap[0] = Ps[mb + r4    ][ks * 8 + c4    ];
            ap[1] = Ps[mb + r4 + 8][ks * 8 + c4    ];
            ap[2] = Ps[mb + r4    ][ks * 8 + c4 + 4];
            ap[3] = Ps[mb + r4 + 8][ks * 8 + c4 + 4];
#pragma unroll
            for (int dt = 0; dt < 8; dt++) {
                uint32_t bv[2];
                bv[0] = Vs[ks * 8 + c4    ][dt * 8 + r4];
                bv[1] = Vs[ks * 8 + c4 + 4][dt * 8 + r4];
                mma16n8k8(oacc[dt], ap, bv);
            }
        }
    }

    const float inv0 = 1.0f / l2[0];
    const float inv1 = 1.0f / l2[1];
#pragma unroll
    for (int dt = 0; dt < 8; dt++) {
        const int d = dt * 8 + 2 * c4;
        float* o0 = g_attn + ((size_t)(b * SEQ + qi0) * HN + h) * HDIM + d;
        float* o1 = g_attn + ((size_t)(b * SEQ + qi1) * HN + h) * HDIM + d;
        *(float2*)o0 = make_float2(oacc[dt][0] * inv0, oacc[dt][1] * inv0);
        *(float2*)o1 = make_float2(oacc[dt][2] * inv1, oacc[dt][3] * inv1);
    }
}

// ---------------------------------------------------------------------------
extern "C" void kernel_launch(void* const* d_in, const int* in_sizes, int n_in,
                              void* d_out, int out_size)
{
    const float* hs = (const float*)d_in[0];
    const float* Wq = (const float*)d_in[1];
    const float* Wk = (const float*)d_in[2];
    const float* Wv = (const float*)d_in[3];
    const float* Wo = (const float*)d_in[4];
    float* out = (float*)d_out;

    float *qp, *kp, *vp, *ap;
    cudaGetSymbolAddress((void**)&qp, g_q);
    cudaGetSymbolAddress((void**)&kp, g_k);
    cudaGetSymbolAddress((void**)&vp, g_v);
    cudaGetSymbolAddress((void**)&ap, g_attn);

    const int M = BATCH * SEQ;   // 4096
    dim3 blk(256);

    build_rope_table<<<(SEQ * 32) / 256, 256>>>();

    // Fused QKV projections (cp.async double-buffered tf32 MMA)
    gemm_qkv<<<dim3((HN * HDIM) / 128, M / 128, 3), blk>>>(hs, Wq, Wk, Wv,
                                                           qp, kp, vp);

    // RoPE from precomputed table
    rope_apply<<<(BATCH * HN * SEQ * 32) / 256, 256>>>(qp, BATCH * HN);
    rope_apply<<<(BATCH * KVN * SEQ * 32) / 256, 256>>>(kp, BATCH * KVN);

    // Attention (tf32 MMA flash)
    cudaFuncSetAttribute(attn_mma,
                         cudaFuncAttributeMaxDynamicSharedMemorySize,
                         ATTN_SMEM_BYTES);
    attn_mma<<<dim3(SEQ / 64, HN, BATCH), 128, ATTN_SMEM_BYTES>>>();

    // Output projection
    gemm_out<<<dim3(DM / 128, M / 128), blk>>>(ap, Wo, out);
}